// round 6
// baseline (speedup 1.0000x reference)
#include <cuda_runtime.h>

#define BB 16
#define SS 4096
#define HH 768
#define NSL 128                 // slices per batch
#define LL 32                   // rows (positions) per slice
#define NCHK 8                  // final-stage chunks per batch
#define CHKSZ (NSL / NCHK)      // 16 partials per chunk
#define NEGV (-1e30f)

// ---------------- scratch (static device globals; no allocation) ----------------
__device__ float g_part[BB * NSL * 9];    // per-slice 3x3 semiring partial products
__device__ float g_nump[BB * NSL];        // numerator partial sums (steps t>=1)
__device__ int   g_mskp[BB * NSL];        // mask partial sums (steps t>=1)
__device__ float g_em0[BB * 3];           // emissions row 0 per batch
__device__ float g_part2[BB * NCHK * 9];  // stage-A chunk products
__device__ float g_nump2[BB * NCHK];
__device__ int   g_mskp2[BB * NCHK];
__device__ unsigned int g_cnt[BB];        // last-block-done counters (reset by fused)

__device__ __forceinline__ float lse3(float a, float b, float c) {
    float m = fmaxf(a, fmaxf(b, c));
    return m + __logf(__expf(a - m) + __expf(b - m) + __expf(c - m));
}

// ---------------- fused kernel: emissions (smem) + blocked CRF scan --------------
__global__ void __launch_bounds__(256, 6) fused_kernel(const float* __restrict__ x,
                                                       const float* __restrict__ W,
                                                       const float* __restrict__ bias,
                                                       const int*   __restrict__ y,
                                                       const int*   __restrict__ mask,
                                                       const float* __restrict__ trans,
                                                       float* __restrict__ out) {
    __shared__ float s_em[LL][4];

    int b     = blockIdx.x >> 7;
    int slice = blockIdx.x & (NSL - 1);
    int tid   = threadIdx.x;
    int wid   = tid >> 5;
    int lane  = tid & 31;
    int R     = b * SS + slice * LL;        // global row base for this block

    if (blockIdx.x == 0) {
        if (tid == 0) out[0] = 0.f;         // zero accumulator for final kernel
        if (tid < BB) g_cnt[tid] = 0u;      // reset last-block counters (graph replay safe)
    }

    // ---- emissions phase: warp wid computes rows R + wid*4 .. +3 ----
    {
        int row0 = R + wid * 4;
        const float4* x4 = reinterpret_cast<const float4*>(x);
        const float4* w4 = reinterpret_cast<const float4*>(W);

        float a0[4], a1[4], a2[4];
#pragma unroll
        for (int r = 0; r < 4; r++) { a0[r] = 0.f; a1[r] = 0.f; a2[r] = 0.f; }

#pragma unroll
        for (int j = 0; j < 6; j++) {
            int idx = lane + 32 * j;          // 0..191
            float4 w0 = __ldg(w4 + idx);
            float4 w1 = __ldg(w4 + 192 + idx);
            float4 w2 = __ldg(w4 + 384 + idx);
#pragma unroll
            for (int r = 0; r < 4; r++) {
                float4 xv = __ldg(x4 + (size_t)(row0 + r) * (HH / 4) + idx);
                a0[r] = fmaf(xv.x, w0.x, fmaf(xv.y, w0.y, fmaf(xv.z, w0.z, fmaf(xv.w, w0.w, a0[r]))));
                a1[r] = fmaf(xv.x, w1.x, fmaf(xv.y, w1.y, fmaf(xv.z, w1.z, fmaf(xv.w, w1.w, a1[r]))));
                a2[r] = fmaf(xv.x, w2.x, fmaf(xv.y, w2.y, fmaf(xv.z, w2.z, fmaf(xv.w, w2.w, a2[r]))));
            }
        }
#pragma unroll
        for (int off = 16; off; off >>= 1) {
#pragma unroll
            for (int r = 0; r < 4; r++) {
                a0[r] += __shfl_xor_sync(0xFFFFFFFFu, a0[r], off);
                a1[r] += __shfl_xor_sync(0xFFFFFFFFu, a1[r], off);
                a2[r] += __shfl_xor_sync(0xFFFFFFFFu, a2[r], off);
            }
        }
        float b0 = __ldg(bias + 0), b1 = __ldg(bias + 1), b2 = __ldg(bias + 2);
#pragma unroll
        for (int r = 0; r < 4; r++) {
            if (lane == r) {
                int lr = wid * 4 + r;
                s_em[lr][0] = a0[r] + b0;
                s_em[lr][1] = a1[r] + b1;
                s_em[lr][2] = a2[r] + b2;
            }
        }
    }
    __syncthreads();

    // ---- scan phase: warp 0 only ----
    if (wid == 0) {
        int s_idx = slice * LL + lane;   // position within sequence
        int t     = R + lane;            // flat index

        float tr[9];
#pragma unroll
        for (int i = 0; i < 9; i++) tr[i] = __ldg(trans + i);

        float P[9];
        float nsum = 0.f;
        int   msum = 0;

        int mk = mask[t];
        if (s_idx > 0 && mk) {
            float e0 = s_em[lane][0], e1 = s_em[lane][1], e2 = s_em[lane][2];
#pragma unroll
            for (int i = 0; i < 3; i++) {
                P[i * 3 + 0] = tr[i * 3 + 0] + e0;
                P[i * 3 + 1] = tr[i * 3 + 1] + e1;
                P[i * 3 + 2] = tr[i * 3 + 2] + e2;
            }
            int yt = y[t], yp = y[t - 1];
            nsum = tr[yp * 3 + yt] + s_em[lane][yt];
            msum = 1;
        } else {
#pragma unroll
            for (int i = 0; i < 9; i++) P[i] = NEGV;
            P[0] = 0.f; P[4] = 0.f; P[8] = 0.f;
        }

        if (s_idx == 0 && lane == 0) {
            g_em0[b * 3 + 0] = s_em[0][0];
            g_em0[b * 3 + 1] = s_em[0][1];
            g_em0[b * 3 + 2] = s_em[0][2];
        }

        // order-preserving suffix tree: lane 0 ends with the whole slice product.
#pragma unroll
        for (int st = 1; st < 32; st <<= 1) {
            float Q[9];
#pragma unroll
            for (int i = 0; i < 9; i++) Q[i] = __shfl_down_sync(0xFFFFFFFFu, P[i], st);
            float nq = __shfl_down_sync(0xFFFFFFFFu, nsum, st);
            int   mq = __shfl_down_sync(0xFFFFFFFFu, msum, st);
            float C[9];
#pragma unroll
            for (int i = 0; i < 3; i++) {
#pragma unroll
                for (int j = 0; j < 3; j++) {
                    C[i * 3 + j] = lse3(P[i * 3 + 0] + Q[0 * 3 + j],
                                        P[i * 3 + 1] + Q[1 * 3 + j],
                                        P[i * 3 + 2] + Q[2 * 3 + j]);
                }
            }
#pragma unroll
            for (int i = 0; i < 9; i++) P[i] = C[i];
            nsum += nq;
            msum += mq;
        }

        if (lane == 0) {
            int pi = b * NSL + slice;
#pragma unroll
            for (int i = 0; i < 9; i++) g_part[pi * 9 + i] = P[i];
            g_nump[pi] = nsum;
            g_mskp[pi] = msum;
        }
    }
}

// ---------------- final kernel: 2-stage entry-parallel reduction ------------------
// grid = BB*NCHK blocks x 256. Stage A: block (b,chunk) tree-reduces its 16 slice
// partials (entry-parallel: 1 lse3/thread/level, depth 4). The LAST block per batch
// (atomic counter) then reduces the 8 chunk products (depth 3) and finishes.
__global__ void __launch_bounds__(256) crf_final_kernel(const int* __restrict__ y,
                                                        const int* __restrict__ mask,
                                                        const float* __restrict__ start_t,
                                                        const float* __restrict__ end_t,
                                                        float* __restrict__ out) {
    __shared__ float sM[CHKSZ * 9];
    __shared__ float sN[CHKSZ];
    __shared__ int   sK[CHKSZ];
    __shared__ float tM[NCHK * 9];
    __shared__ float tN[NCHK];
    __shared__ int   tK[NCHK];
    __shared__ int   s_last;

    int b     = blockIdx.x >> 3;
    int chunk = blockIdx.x & (NCHK - 1);
    int tid   = threadIdx.x;
    int base  = b * NSL + chunk * CHKSZ;

    if (tid < CHKSZ * 9) sM[tid] = g_part[base * 9 + tid];
    if (tid < CHKSZ) { sN[tid] = g_nump[base + tid]; sK[tid] = g_mskp[base + tid]; }
    __syncthreads();

    // ---- stage A: tree over 16 partials ----
    for (int st = 1; st < CHKSZ; st <<= 1) {
        int pairs = CHKSZ / (2 * st);
        int jobs  = pairs * 9;
        float cv = 0.f; int off = 0;
        bool doj = tid < jobs;
        if (doj) {
            int p = tid / 9, e = tid - p * 9;
            int i = e / 3, c = e - i * 3;
            int m = p * 2 * st;
            const float* A  = &sM[m * 9];
            const float* Bm = &sM[(m + st) * 9];
            cv  = lse3(A[i * 3 + 0] + Bm[0 + c],
                       A[i * 3 + 1] + Bm[3 + c],
                       A[i * 3 + 2] + Bm[6 + c]);
            off = m * 9 + e;
        }
        bool dos = tid < pairs;
        float nv = 0.f; int kv = 0;
        if (dos) { int m = tid * 2 * st; nv = sN[m] + sN[m + st]; kv = sK[m] + sK[m + st]; }
        __syncthreads();
        if (doj) sM[off] = cv;
        if (dos) { int m = tid * 2 * st; sN[m] = nv; sK[m] = kv; }
        __syncthreads();
    }

    int ci = b * NCHK + chunk;
    if (tid < 9) g_part2[ci * 9 + tid] = sM[tid];
    if (tid == 0) { g_nump2[ci] = sN[0]; g_mskp2[ci] = sK[0]; }
    __threadfence();
    if (tid == 0) {
        unsigned int old = atomicAdd(&g_cnt[b], 1u);
        s_last = (old == NCHK - 1u) ? 1 : 0;
    }
    __syncthreads();
    if (!s_last) return;

    // ---- stage B (last block of batch b): tree over 8 chunk products ----
    if (tid < NCHK * 9) tM[tid] = __ldcg(&g_part2[b * NCHK * 9 + tid]);
    if (tid < NCHK) { tN[tid] = __ldcg(&g_nump2[b * NCHK + tid]); tK[tid] = __ldcg(&g_mskp2[b * NCHK + tid]); }
    __syncthreads();

    for (int st = 1; st < NCHK; st <<= 1) {
        int pairs = NCHK / (2 * st);
        int jobs  = pairs * 9;
        float cv = 0.f; int off = 0;
        bool doj = tid < jobs;
        if (doj) {
            int p = tid / 9, e = tid - p * 9;
            int i = e / 3, c = e - i * 3;
            int m = p * 2 * st;
            const float* A  = &tM[m * 9];
            const float* Bm = &tM[(m + st) * 9];
            cv  = lse3(A[i * 3 + 0] + Bm[0 + c],
                       A[i * 3 + 1] + Bm[3 + c],
                       A[i * 3 + 2] + Bm[6 + c]);
            off = m * 9 + e;
        }
        bool dos = tid < pairs;
        float nv = 0.f; int kv = 0;
        if (dos) { int m = tid * 2 * st; nv = tN[m] + tN[m + st]; kv = tK[m] + tK[m + st]; }
        __syncthreads();
        if (doj) tM[off] = cv;
        if (dos) { int m = tid * 2 * st; tN[m] = nv; tK[m] = kv; }
        __syncthreads();
    }

    if (tid == 0) {
        int bS = b * SS;
        float e0 = g_em0[b * 3 + 0], e1 = g_em0[b * 3 + 1], e2 = g_em0[b * 3 + 2];
        float a0 = start_t[0] + e0;
        float a1 = start_t[1] + e1;
        float a2 = start_t[2] + e2;

        float af0 = lse3(a0 + tM[0], a1 + tM[3], a2 + tM[6]);
        float af1 = lse3(a0 + tM[1], a1 + tM[4], a2 + tM[7]);
        float af2 = lse3(a0 + tM[2], a1 + tM[5], a2 + tM[8]);
        float denom = lse3(af0 + end_t[0], af1 + end_t[1], af2 + end_t[2]);

        int y0 = y[bS];
        float em0y = (y0 == 0) ? e0 : ((y0 == 1) ? e1 : e2);
        float num  = start_t[y0] + em0y + tN[0];
        int   slen = mask[bS] + tK[0];
        num += end_t[y[bS + slen - 1]];

        atomicAdd(out, -(num - denom) / (float)BB);
    }
}

// ---------------- launch ----------------------------------------------------------
extern "C" void kernel_launch(void* const* d_in, const int* in_sizes, int n_in,
                              void* d_out, int out_size) {
    const float* x     = (const float*)d_in[0];
    const int*   y     = (const int*)  d_in[1];
    const int*   mask  = (const int*)  d_in[2];
    const float* W     = (const float*)d_in[3];
    const float* bias  = (const float*)d_in[4];
    const float* st    = (const float*)d_in[5];
    const float* en    = (const float*)d_in[6];
    const float* trans = (const float*)d_in[7];
    float* out = (float*)d_out;

    fused_kernel<<<BB * NSL, 256>>>(x, W, bias, y, mask, trans, out);
    crf_final_kernel<<<BB * NCHK, 256>>>(y, mask, st, en, out);
}

// round 8
// speedup vs baseline: 1.0323x; 1.0323x over previous
#include <cuda_runtime.h>

#define BB 16
#define SS 4096
#define HH 768
#define NSL 128                 // slices per batch
#define LL 32                   // rows (positions) per slice
#define NEGV (-1e30f)

// ---------------- scratch (static device globals; no allocation) ----------------
__device__ float g_part[BB * NSL * 9];    // per-slice 3x3 semiring partial products
__device__ float g_nump[BB * NSL];        // numerator partial sums (steps t>=1)
__device__ int   g_mskp[BB * NSL];        // mask partial sums (steps t>=1)
__device__ float g_em0[BB * 3];           // emissions row 0 per batch
__device__ float g_llh[BB];               // per-batch log-likelihood
__device__ unsigned int g_cnt[BB];        // per-batch arrival counters (monotonic, mod 128)
__device__ unsigned int g_bcnt;           // batch-finalize counter (monotonic, mod 16)

__device__ __forceinline__ float lse3(float a, float b, float c) {
    float m = fmaxf(a, fmaxf(b, c));
    return m + __logf(__expf(a - m) + __expf(b - m) + __expf(c - m));
}

// ---------------- single fused kernel: emissions + scan + finalize ----------------
// grid = BB*NSL blocks of 256. Block (b,slice) owns rows [slice*32, slice*32+32).
// Phase 1: 8 warps x 4 rows compute emissions into smem.
// Phase 2: warp 0 scans its 32 steps via shuffle tree, writes slice partial.
// Phase 3: the LAST block of each batch (atomic counter) tree-reduces the 128
//          partials; the last batch-finalizer writes out[0]. Counters are
//          monotonic (checked mod 128 / mod 16) so graph replays are safe.
__global__ void __launch_bounds__(256, 5) fused_kernel(const float* __restrict__ x,
                                                       const float* __restrict__ W,
                                                       const float* __restrict__ bias,
                                                       const int*   __restrict__ y,
                                                       const int*   __restrict__ mask,
                                                       const float* __restrict__ trans,
                                                       const float* __restrict__ start_t,
                                                       const float* __restrict__ end_t,
                                                       float* __restrict__ out) {
    __shared__ float s_em[LL][4];
    __shared__ float sM[NSL * 9];
    __shared__ float sN[NSL];
    __shared__ int   sK[NSL];
    __shared__ int   s_flag;

    int b     = blockIdx.x >> 7;
    int slice = blockIdx.x & (NSL - 1);
    int tid   = threadIdx.x;
    int wid   = tid >> 5;
    int lane  = tid & 31;
    int R     = b * SS + slice * LL;        // global row base for this block

    // ---- phase 1: emissions. warp wid computes rows R + wid*4 .. +3 ----
    {
        int row0 = R + wid * 4;
        const float4* x4 = reinterpret_cast<const float4*>(x);
        const float4* w4 = reinterpret_cast<const float4*>(W);

        float a0[4], a1[4], a2[4];
#pragma unroll
        for (int r = 0; r < 4; r++) { a0[r] = 0.f; a1[r] = 0.f; a2[r] = 0.f; }

#pragma unroll
        for (int j = 0; j < 6; j++) {
            int idx = lane + 32 * j;          // 0..191
            float4 w0 = __ldg(w4 + idx);
            float4 w1 = __ldg(w4 + 192 + idx);
            float4 w2 = __ldg(w4 + 384 + idx);
#pragma unroll
            for (int r = 0; r < 4; r++) {
                float4 xv = __ldg(x4 + (size_t)(row0 + r) * (HH / 4) + idx);
                a0[r] = fmaf(xv.x, w0.x, fmaf(xv.y, w0.y, fmaf(xv.z, w0.z, fmaf(xv.w, w0.w, a0[r]))));
                a1[r] = fmaf(xv.x, w1.x, fmaf(xv.y, w1.y, fmaf(xv.z, w1.z, fmaf(xv.w, w1.w, a1[r]))));
                a2[r] = fmaf(xv.x, w2.x, fmaf(xv.y, w2.y, fmaf(xv.z, w2.z, fmaf(xv.w, w2.w, a2[r]))));
            }
        }
#pragma unroll
        for (int off = 16; off; off >>= 1) {
#pragma unroll
            for (int r = 0; r < 4; r++) {
                a0[r] += __shfl_xor_sync(0xFFFFFFFFu, a0[r], off);
                a1[r] += __shfl_xor_sync(0xFFFFFFFFu, a1[r], off);
                a2[r] += __shfl_xor_sync(0xFFFFFFFFu, a2[r], off);
            }
        }
        float b0 = __ldg(bias + 0), b1 = __ldg(bias + 1), b2 = __ldg(bias + 2);
#pragma unroll
        for (int r = 0; r < 4; r++) {
            if (lane == r) {
                int lr = wid * 4 + r;
                s_em[lr][0] = a0[r] + b0;
                s_em[lr][1] = a1[r] + b1;
                s_em[lr][2] = a2[r] + b2;
            }
        }
    }
    __syncthreads();

    // ---- phase 2: scan (warp 0 only). All global writes by tid 0. ----
    if (wid == 0) {
        int s_idx = slice * LL + lane;   // position within sequence
        int t     = R + lane;            // flat index

        float tr[9];
#pragma unroll
        for (int i = 0; i < 9; i++) tr[i] = __ldg(trans + i);

        float P[9];
        float nsum = 0.f;
        int   msum = 0;

        int mk = mask[t];
        if (s_idx > 0 && mk) {
            float e0 = s_em[lane][0], e1 = s_em[lane][1], e2 = s_em[lane][2];
#pragma unroll
            for (int i = 0; i < 3; i++) {
                P[i * 3 + 0] = tr[i * 3 + 0] + e0;
                P[i * 3 + 1] = tr[i * 3 + 1] + e1;
                P[i * 3 + 2] = tr[i * 3 + 2] + e2;
            }
            int yt = y[t], yp = y[t - 1];
            nsum = tr[yp * 3 + yt] + s_em[lane][yt];
            msum = 1;
        } else {
#pragma unroll
            for (int i = 0; i < 9; i++) P[i] = NEGV;
            P[0] = 0.f; P[4] = 0.f; P[8] = 0.f;
        }

        // order-preserving suffix tree: lane 0 ends with the whole slice product.
#pragma unroll
        for (int st = 1; st < 32; st <<= 1) {
            float Q[9];
#pragma unroll
            for (int i = 0; i < 9; i++) Q[i] = __shfl_down_sync(0xFFFFFFFFu, P[i], st);
            float nq = __shfl_down_sync(0xFFFFFFFFu, nsum, st);
            int   mq = __shfl_down_sync(0xFFFFFFFFu, msum, st);
            float C[9];
#pragma unroll
            for (int i = 0; i < 3; i++) {
#pragma unroll
                for (int j = 0; j < 3; j++) {
                    C[i * 3 + j] = lse3(P[i * 3 + 0] + Q[0 * 3 + j],
                                        P[i * 3 + 1] + Q[1 * 3 + j],
                                        P[i * 3 + 2] + Q[2 * 3 + j]);
                }
            }
#pragma unroll
            for (int i = 0; i < 9; i++) P[i] = C[i];
            nsum += nq;
            msum += mq;
        }

        if (lane == 0) {
            if (slice == 0) {
                g_em0[b * 3 + 0] = s_em[0][0];
                g_em0[b * 3 + 1] = s_em[0][1];
                g_em0[b * 3 + 2] = s_em[0][2];
            }
            int pi = b * NSL + slice;
#pragma unroll
            for (int i = 0; i < 9; i++) g_part[pi * 9 + i] = P[i];
            g_nump[pi] = nsum;
            g_mskp[pi] = msum;
        }
    }
    __syncthreads();

    // ---- phase 3: last block of batch b finalizes ----
    if (tid == 0) {
        __threadfence();                                   // publish tid0's writes
        unsigned int old = atomicAdd(&g_cnt[b], 1u);
        s_flag = ((old & (NSL - 1u)) == NSL - 1u) ? 1 : 0; // mod 128 (graph replays)
    }
    __syncthreads();
    if (!s_flag) return;

    // load all 128 slice partials (writers fenced before their bumps)
    for (int i = tid; i < NSL * 9; i += 256) sM[i] = __ldcg(&g_part[b * NSL * 9 + i]);
    if (tid < NSL) {
        sN[tid] = __ldcg(&g_nump[b * NSL + tid]);
        sK[tid] = __ldcg(&g_mskp[b * NSL + tid]);
    }
    __syncthreads();

    // entry-parallel tree: depth 7, one lse3 per thread-job per level
    for (int st = 1; st < NSL; st <<= 1) {
        int pairs = NSL / (2 * st);
        int jobs  = pairs * 9;
        float Cv[3]; int off[3]; int cnt = 0;
        for (int j = tid; j < jobs; j += 256) {
            int p = j / 9, e = j - p * 9;
            int i = e / 3, c = e - i * 3;
            int m = p * 2 * st;
            const float* A  = &sM[m * 9];
            const float* Bm = &sM[(m + st) * 9];
            Cv[cnt]  = lse3(A[i * 3 + 0] + Bm[0 + c],
                            A[i * 3 + 1] + Bm[3 + c],
                            A[i * 3 + 2] + Bm[6 + c]);
            off[cnt] = m * 9 + e;
            cnt++;
        }
        bool dos = tid < pairs;
        float nv = 0.f; int kv = 0;
        if (dos) { int m = tid * 2 * st; nv = sN[m] + sN[m + st]; kv = sK[m] + sK[m + st]; }
        __syncthreads();
        for (int q = 0; q < cnt; q++) sM[off[q]] = Cv[q];
        if (dos) { int m = tid * 2 * st; sN[m] = nv; sK[m] = kv; }
        __syncthreads();
    }

    if (tid == 0) {
        int bS = b * SS;
        float e0 = __ldcg(&g_em0[b * 3 + 0]);
        float e1 = __ldcg(&g_em0[b * 3 + 1]);
        float e2 = __ldcg(&g_em0[b * 3 + 2]);
        float a0 = start_t[0] + e0;
        float a1 = start_t[1] + e1;
        float a2 = start_t[2] + e2;

        float af0 = lse3(a0 + sM[0], a1 + sM[3], a2 + sM[6]);
        float af1 = lse3(a0 + sM[1], a1 + sM[4], a2 + sM[7]);
        float af2 = lse3(a0 + sM[2], a1 + sM[5], a2 + sM[8]);
        float denom = lse3(af0 + end_t[0], af1 + end_t[1], af2 + end_t[2]);

        int y0 = y[bS];
        float em0y = (y0 == 0) ? e0 : ((y0 == 1) ? e1 : e2);
        float num  = start_t[y0] + em0y + sN[0];
        int   slen = mask[bS] + sK[0];
        num += end_t[y[bS + slen - 1]];

        g_llh[b] = num - denom;
        __threadfence();
        unsigned int ob = atomicAdd(&g_bcnt, 1u);
        if ((ob & (BB - 1u)) == BB - 1u) {                 // 16th batch-finalizer
            float s = 0.f;
#pragma unroll
            for (int i = 0; i < BB; i++) s += __ldcg(&g_llh[i]);
            out[0] = -s / (float)BB;
        }
    }
}

// ---------------- launch ----------------------------------------------------------
extern "C" void kernel_launch(void* const* d_in, const int* in_sizes, int n_in,
                              void* d_out, int out_size) {
    const float* x     = (const float*)d_in[0];
    const int*   y     = (const int*)  d_in[1];
    const int*   mask  = (const int*)  d_in[2];
    const float* W     = (const float*)d_in[3];
    const float* bias  = (const float*)d_in[4];
    const float* st    = (const float*)d_in[5];
    const float* en    = (const float*)d_in[6];
    const float* trans = (const float*)d_in[7];
    float* out = (float*)d_out;

    fused_kernel<<<BB * NSL, 256>>>(x, W, bias, y, mask, trans, st, en, out);
}